// round 5
// baseline (speedup 1.0000x reference)
#include <cuda_runtime.h>

#define Bn 32
#define Nn 4096
#define Kn 16
#define PTS 128                 // points per block
#define NBLK (Nn / PTS)         // 32 blocks per batch
#define GRIDA (Bn * NBLK)       // 1024 blocks

// Deterministic scratch (no allocations allowed)
__device__ float g_comb[GRIDA];             // rec + kld partial (pre-weighted)
__device__ float g_col_partial[GRIDA * Kn]; // assign column partials
__device__ unsigned int g_count = 0;

__device__ __forceinline__ float flog2(float x) {
    float y; asm("lg2.approx.f32 %0, %1;" : "=f"(y) : "f"(x)); return y;
}
__device__ __forceinline__ float fexp2(float x) {
    float y; asm("ex2.approx.f32 %0, %1;" : "=f"(y) : "f"(x)); return y;
}

__global__ __launch_bounds__(256) void loss_fused_kernel(
    const float* __restrict__ pc, const float* __restrict__ normals,
    const float* __restrict__ randn, const float* __restrict__ scale,
    const float* __restrict__ shapes, const float* __restrict__ rotate,
    const float* __restrict__ pam, const float* __restrict__ assign,
    const float* __restrict__ exist, const float* __restrict__ mu,
    const float* __restrict__ logvar, const float* __restrict__ trans,
    float* __restrict__ out)
{
    // sP stride 20 (80B, 16B-aligned): [0-8]=R, [9-11]=scale, [12-13]=he, [14-16]=cc=R^T mean
    __shared__ __align__(16) float sP[Kn * 20];
    __shared__ float sM[Kn * 3];          // raw means (staging only)
    __shared__ float sA[PTS * 17];        // assign rows, stride-17 (conflict-free)
    __shared__ __align__(16) float sPC[PTS * 3];
    __shared__ __align__(16) float sNM[PTS * 3];
    __shared__ __align__(16) float sRD[PTS];
    __shared__ float scol2[256];
    __shared__ float srec[8];
    __shared__ float skld[4];
    __shared__ float sfin[512];
    __shared__ bool  isLast;

    const int blk   = blockIdx.x;
    const int b     = blk >> 5;          // batch
    const int t     = threadIdx.x;
    const int lane  = t & 31;
    const int warp  = t >> 5;
    const int nl    = t & (PTS - 1);     // local point id
    const int khalf = t >> 7;            // 0: k in [0,8), 1: k in [8,16)

    // Stage per-(b,k) parameters (he = 0.5 * shape exponent)
    if (t < 144) sP[(t / 9) * 20 + (t % 9)]      = rotate[b * 144 + t];
    if (t < 48)  sP[(t / 3) * 20 + 9 + (t % 3)]  = scale [b * 48  + t];
    if (t < 32)  sP[(t / 2) * 20 + 12 + (t % 2)] = 0.5f * shapes[b * 32 + t];
    if (t < 48)  sM[t]                           = pam   [b * 48  + t];

    // Stage assign rows: each thread loads half a row (8 floats)
    {
        const int row = t >> 1, half = t & 1;
        const float4* ar = reinterpret_cast<const float4*>(assign)
                         + ((size_t)b * Nn + (blk & 31) * PTS + row) * 4 + half * 2;
        float4 a0 = ar[0], a1 = ar[1];
        float* dst = sA + row * 17 + half * 8;
        dst[0] = a0.x; dst[1] = a0.y; dst[2] = a0.z; dst[3] = a0.w;
        dst[4] = a1.x; dst[5] = a1.y; dst[6] = a1.z; dst[7] = a1.w;
    }

    // Stage pc / normals (384 floats each = 96 float4 each) and randn (32 float4)
    {
        const size_t base3 = ((size_t)b * Nn + (blk & 31) * PTS) * 3;  // 1536B-aligned
        const float4* pcv = reinterpret_cast<const float4*>(pc + base3);
        const float4* nmv = reinterpret_cast<const float4*>(normals + base3);
        if (t < 96)  reinterpret_cast<float4*>(sPC)[t] = pcv[t];
        else if (t < 192) reinterpret_cast<float4*>(sNM)[t - 96] = nmv[t - 96];
        else if (t < 224) {
            const float4* rdv = reinterpret_cast<const float4*>(randn + (size_t)b * Nn + (blk & 31) * PTS);
            reinterpret_cast<float4*>(sRD)[t - 192] = rdv[t - 192];
        } else if (t < 228) {
            const int id = blk * 4 + (t - 224);
            const float lv = logvar[id], m = mu[id];
            skld[t - 224] = 1.f + lv - m * m - expf(lv);
        }
    }
    __syncthreads();

    // cc = R^T mean  (48 threads, one component each)
    if (t < 48) {
        const int k = t / 3, i = t % 3;
        const float* R = sP + k * 20;
        const float* m = sM + k * 3;
        sP[k * 20 + 14 + i] = R[i] * m[0] + R[3 + i] * m[1] + R[6 + i] * m[2];
    }
    __syncthreads();

    const float px = sPC[nl * 3], py = sPC[nl * 3 + 1], pz = sPC[nl * 3 + 2];
    const float nx = sNM[nl * 3], ny = sNM[nl * 3 + 1], nz = sNM[nl * 3 + 2];
    const float nn  = nx * nx + ny * ny + nz * nz;
    const float inl = rsqrtf(nn);
    const float hx = nx * inl, hy = ny * inl, hz = nz * inl;   // unit normal
    const float rn = sRD[nl] * 0.01f * nn * inl;               // noise * ||normals||

    float rec = 0.f;
    const float* arow = sA + nl * 17;

    #pragma unroll
    for (int kk = 0; kk < 8; kk++) {
        const int k = khalf * 8 + kk;
        const float4* Pv = reinterpret_cast<const float4*>(sP + k * 20);
        const float4 f0 = Pv[0];   // R0 R1 R2 R3
        const float4 f1 = Pv[1];   // R4 R5 R6 R7
        const float4 f2 = Pv[2];   // R8 s0 s1 s2
        const float4 f3 = Pv[3];   // he0 he1 cc0 cc1
        const float cc2 = sP[k * 20 + 16];
        const float R0 = f0.x, R1 = f0.y, R2 = f0.z, R3 = f0.w;
        const float R4 = f1.x, R5 = f1.y, R6 = f1.z, R7 = f1.w;
        const float R8 = f2.x, s0 = f2.y, s1 = f2.z, s2 = f2.w;
        const float he0 = f3.x, he1 = f3.y, cc0 = f3.z, cc1 = f3.w;

        // pci = R^T pc - R^T mean (cc folded into FMA seed)
        const float c0 = fmaf(R0, px, fmaf(R3, py, fmaf(R6, pz, -cc0)));
        const float c1 = fmaf(R1, px, fmaf(R4, py, fmaf(R7, pz, -cc1)));
        const float c2 = fmaf(R2, px, fmaf(R5, py, fmaf(R8, pz, -cc2)));
        // w = R^T nhat
        const float w0 = fmaf(R0, hx, fmaf(R3, hy, R6 * hz));
        const float w1 = fmaf(R1, hx, fmaf(R4, hy, R7 * hz));
        const float w2 = fmaf(R2, hx, fmaf(R5, hy, R8 * hz));
        // psi = pci + rn * w
        const float q0 = fmaf(rn, w0, c0);
        const float q1 = fmaf(rn, w1, c1);
        const float q2 = fmaf(rn, w2, c2);

        // argmax over 6 faces == max |w| axis, sign = (w>0 ? + : -)
        const float a0 = fabsf(w0), a1 = fabsf(w1), a2 = fabsf(w2);
        int ax = 0; float best = a0;
        if (a1 > best) { best = a1; ax = 1; }
        if (a2 > best) { best = a2; ax = 2; }
        const float wax = (ax == 0) ? w0 : ((ax == 1) ? w1 : w2);
        const float sgn = (wax > 0.f) ? 1.f : -1.f;

        // clamp, then override selected axis with +/- scale
        float p0 = fminf(fmaxf(q0, -s0), s0);
        float p1 = fminf(fmaxf(q1, -s1), s1);
        float p2 = fminf(fmaxf(q2, -s2), s2);
        if (ax == 0)      p0 = sgn * s0;
        else if (ax == 1) p1 = sgn * s1;
        else              p2 = sgn * s2;

        // log-domain superquadric surface point
        const float p0sq = fmaxf(p0 * p0, 1e-38f);
        const float p1sq = fmaxf(p1 * p1, 1e-38f);
        const float p2sq = fmaxf(p2 * p2, 1e-38f);
        const float r2   = p0sq + p1sq;
        const float rho2 = r2 + p2sq;          // >= min(scale)^2 >= 0.01

        const float Lr = flog2(r2);
        const float Lh = flog2(rho2);
        const float L0 = flog2(p0sq);
        const float L1 = flog2(p1sq);
        const float L2 = flog2(p2sq);

        const float tphi = he0 * (Lr - Lh);            // log2(gph)
        const float u    = fmaf(-he1, Lr, tphi);
        const float X = copysignf(s0 * fexp2(fmaf(he1, L0, u)), p0);
        const float Y = copysignf(s1 * fexp2(fmaf(he1, L1, u)), p1);
        const float Z = copysignf(s2 * fexp2(he0 * (L2 - Lh)), p2);

        const float dx = X - c0, dy = Y - c1, dz = Z - c2;
        rec = fmaf(dx * dx + dy * dy + dz * dz, arow[k], rec);
    }

    // --- block reductions (deterministic) ---
    #pragma unroll
    for (int off = 16; off; off >>= 1)
        rec += __shfl_down_sync(0xffffffffu, rec, off);
    if (lane == 0) srec[warp] = rec;

    // assign column sums from sA: thread t sums 8 rows of column (t&15)
    {
        const int kcol = t & 15, chunk = t >> 4;   // 16 chunks x 8 rows = 128 rows
        float csum = 0.f;
        #pragma unroll
        for (int i = 0; i < 8; i++)
            csum += sA[(chunk * 8 + i) * 17 + kcol];
        scol2[t] = csum;
    }
    __syncthreads();

    if (t == 0) {
        float s = 0.f;
        #pragma unroll
        for (int w = 0; w < 8; w++) s += srec[w];
        float kp = skld[0] + skld[1] + skld[2] + skld[3];
        g_comb[blk] = s * (1.0f / (32.f * 4096.f)) + kp * (-0.5f * 0.001f / 32.f);
    }
    if (t < Kn) {
        float s = 0.f;
        #pragma unroll
        for (int c = 0; c < 16; c++) s += scol2[t + c * 16];
        g_col_partial[blk * Kn + t] = s;
    }

    // --- last-block-done: fused final reduction ---
    __threadfence();
    __syncthreads();
    if (t == 0) {
        unsigned int v = atomicAdd(&g_count, 1u);
        isLast = (v == GRIDA - 1);
    }
    __syncthreads();
    if (!isLast) return;
    __threadfence();

    float acc = g_comb[t] + g_comb[t + 256] + g_comb[t + 512] + g_comb[t + 768];

    // cs for (b,k) pairs p = t and p = t+256
    float cs0 = 0.f, cs1 = 0.f;
    {
        const int b0 = t >> 4, b1 = (t + 256) >> 4, kc = t & 15;
        #pragma unroll
        for (int nb2 = 0; nb2 < 32; nb2++) {
            cs0 += g_col_partial[((b0 * 32 + nb2) << 4) + kc];
            cs1 += g_col_partial[((b1 * 32 + nb2) << 4) + kc];
        }
        sfin[t]       = sqrtf(cs0 * (1.f / 4096.f) + 0.01f);
        sfin[t + 256] = sqrtf(cs1 * (1.f / 4096.f) + 0.01f);
    }

    // EXT: BCE-with-logits for pairs t, t+256 (weight 0.01)
    {
        const float l0 = exist[t], l1 = exist[t + 256];
        const float g0 = (cs0 > 24.f) ? 1.f : 0.f;
        const float g1 = (cs1 > 24.f) ? 1.f : 0.f;
        const float e0v = fmaxf(l0, 0.f) - l0 * g0 + log1pf(expf(-fabsf(l0)));
        const float e1v = fmaxf(l1, 0.f) - l1 * g1 + log1pf(expf(-fabsf(l1)));
        acc += (e0v + e1v) * (0.01f / 512.f);
    }

    // CST: 512 (b,k) pairs, 2 per thread (weight 0.1)
    {
        const int p0i = t * 3, p1i = (t + 256) * 3;
        float dx0 = pam[p0i]     - trans[p0i];
        float dy0 = pam[p0i + 1] - trans[p0i + 1];
        float dz0 = pam[p0i + 2] - trans[p0i + 2];
        float dx1 = pam[p1i]     - trans[p1i];
        float dy1 = pam[p1i + 1] - trans[p1i + 1];
        float dz1 = pam[p1i + 2] - trans[p1i + 2];
        acc += (sqrtf(dx0 * dx0 + dy0 * dy0 + dz0 * dz0) +
                sqrtf(dx1 * dx1 + dy1 * dy1 + dz1 * dz1)) * (0.1f / 512.f);
    }

    // SPS: per-b mean over k of sfin, squared (weight 0.1)
    __syncthreads();
    if (t < 32) {
        float m = 0.f;
        #pragma unroll
        for (int kk2 = 0; kk2 < 16; kk2++) m += sfin[t * 16 + kk2];
        m *= (1.f / 16.f);
        acc += m * m * (0.1f / 32.f);
    }

    // block reduction of acc
    #pragma unroll
    for (int off = 16; off; off >>= 1)
        acc += __shfl_down_sync(0xffffffffu, acc, off);
    __syncthreads();
    if (lane == 0) srec[warp] = acc;
    __syncthreads();
    if (t == 0) {
        float s = 0.f;
        #pragma unroll
        for (int w = 0; w < 8; w++) s += srec[w];
        out[0] = s;
        g_count = 0;   // reset for next graph replay
    }
}

extern "C" void kernel_launch(void* const* d_in, const int* in_sizes, int n_in,
                              void* d_out, int out_size)
{
    const float* pc      = (const float*)d_in[0];
    const float* normals = (const float*)d_in[1];
    const float* randn   = (const float*)d_in[2];
    const float* scale   = (const float*)d_in[3];
    const float* shapes  = (const float*)d_in[4];
    const float* rotate  = (const float*)d_in[5];
    const float* pam     = (const float*)d_in[6];
    const float* assign  = (const float*)d_in[7];
    const float* exist   = (const float*)d_in[8];
    const float* mu      = (const float*)d_in[9];
    const float* logvar  = (const float*)d_in[10];
    const float* trans   = (const float*)d_in[11];
    float* out = (float*)d_out;

    loss_fused_kernel<<<GRIDA, 256>>>(pc, normals, randn, scale, shapes, rotate,
                                      pam, assign, exist, mu, logvar, trans, out);
}

// round 6
// speedup vs baseline: 1.0677x; 1.0677x over previous
#include <cuda_runtime.h>

#define Bn 32
#define Nn 4096
#define Kn 16
#define PTS 128                 // points per block
#define NBLK (Nn / PTS)         // 32 blocks per batch
#define GRIDA (Bn * NBLK)       // 1024 blocks

// Deterministic scratch (no allocations allowed)
__device__ float g_comb[GRIDA];             // rec + kld partial (pre-weighted)
__device__ float g_col_partial[GRIDA * Kn]; // assign column partials
__device__ unsigned int g_count = 0;

__device__ __forceinline__ float flog2(float x) {
    float y; asm("lg2.approx.f32 %0, %1;" : "=f"(y) : "f"(x)); return y;
}
__device__ __forceinline__ float fexp2(float x) {
    float y; asm("ex2.approx.f32 %0, %1;" : "=f"(y) : "f"(x)); return y;
}

__global__ __launch_bounds__(256, 4) void loss_fused_kernel(
    const float* __restrict__ pc, const float* __restrict__ normals,
    const float* __restrict__ randn, const float* __restrict__ scale,
    const float* __restrict__ shapes, const float* __restrict__ rotate,
    const float* __restrict__ pam, const float* __restrict__ assign,
    const float* __restrict__ exist, const float* __restrict__ mu,
    const float* __restrict__ logvar, const float* __restrict__ trans,
    float* __restrict__ out)
{
    // sP stride 17: [0-8]=R, [9-11]=scale, [12-13]=he, [14-16]=cc = R^T mean
    __shared__ float sP[Kn * 17];
    __shared__ float sM[Kn * 3];         // raw means (staging only)
    __shared__ float sA[PTS * 17];       // assign rows, stride-17 (conflict-free)
    __shared__ float scol2[256];
    __shared__ float srec[8];
    __shared__ float skld[4];
    __shared__ float sfin[512];
    __shared__ bool  isLast;

    const int blk   = blockIdx.x;
    const int b     = blk >> 5;          // batch
    const int t     = threadIdx.x;
    const int lane  = t & 31;
    const int warp  = t >> 5;
    const int nl    = t & (PTS - 1);     // local point id
    const int khalf = t >> 7;            // 0: k in [0,8), 1: k in [8,16)
    const int n     = (blk & 31) * PTS + nl;

    // Stage per-(b,k) parameters (he = 0.5 * shape exponent)
    if (t < 144) sP[(t / 9) * 17 + (t % 9)]      = rotate[b * 144 + t];
    if (t < 48)  sP[(t / 3) * 17 + 9 + (t % 3)]  = scale [b * 48  + t];
    if (t < 32)  sP[(t / 2) * 17 + 12 + (t % 2)] = 0.5f * shapes[b * 32 + t];
    if (t < 48)  sM[t]                           = pam   [b * 48  + t];

    // Stage assign rows into shared (for column sums): half row per thread
    {
        const int row = t >> 1, half = t & 1;
        const float4* ar = reinterpret_cast<const float4*>(assign)
                         + ((size_t)b * Nn + (blk & 31) * PTS + row) * 4 + half * 2;
        float4 a0 = ar[0], a1 = ar[1];
        float* dst = sA + row * 17 + half * 8;
        dst[0] = a0.x; dst[1] = a0.y; dst[2] = a0.z; dst[3] = a0.w;
        dst[4] = a1.x; dst[5] = a1.y; dst[6] = a1.z; dst[7] = a1.w;
    }

    // This thread's 8 assign weights, straight to registers
    float akr[8];
    {
        const float4* av = reinterpret_cast<const float4*>(assign)
                         + ((size_t)b * Nn + n) * 4 + khalf * 2;
        const float4 a0 = av[0], a1 = av[1];
        akr[0] = a0.x; akr[1] = a0.y; akr[2] = a0.z; akr[3] = a0.w;
        akr[4] = a1.x; akr[5] = a1.y; akr[6] = a1.z; akr[7] = a1.w;
    }

    // KLD slice for this block
    if (t < 4) {
        const int id = blk * 4 + t;
        const float lv = logvar[id], m = mu[id];
        skld[t] = 1.f + lv - m * m - expf(lv);
    }
    __syncthreads();

    // cc = R^T mean  (48 threads, one component each)
    if (t < 48) {
        const int k = t / 3, i = t % 3;
        const float* R = sP + k * 17;
        const float* m = sM + k * 3;
        sP[k * 17 + 14 + i] = R[i] * m[0] + R[3 + i] * m[1] + R[6 + i] * m[2];
    }
    __syncthreads();

    const size_t pi = ((size_t)b * Nn + n) * 3;
    const float px = pc[pi], py = pc[pi + 1], pz = pc[pi + 2];
    const float nx = normals[pi], ny = normals[pi + 1], nz = normals[pi + 2];
    const float nn  = nx * nx + ny * ny + nz * nz;
    const float inl = rsqrtf(nn);
    const float hx = nx * inl, hy = ny * inl, hz = nz * inl;   // unit normal
    const float rn = randn[b * Nn + n] * 0.01f * nn * inl;     // noise * ||normals||

    float rec = 0.f;

    #pragma unroll
    for (int kk = 0; kk < 8; kk++) {
        const int k = khalf * 8 + kk;
        const float* P = sP + k * 17;
        const float R0 = P[0], R1 = P[1], R2 = P[2], R3 = P[3], R4 = P[4],
                    R5 = P[5], R6 = P[6], R7 = P[7], R8 = P[8];
        const float s0 = P[9], s1 = P[10], s2 = P[11];
        const float he0 = P[12], he1 = P[13];
        const float cc0 = P[14], cc1 = P[15], cc2 = P[16];

        // pci = R^T pc - R^T mean (cc folded into FMA seed)
        const float c0 = fmaf(R0, px, fmaf(R3, py, fmaf(R6, pz, -cc0)));
        const float c1 = fmaf(R1, px, fmaf(R4, py, fmaf(R7, pz, -cc1)));
        const float c2 = fmaf(R2, px, fmaf(R5, py, fmaf(R8, pz, -cc2)));
        // w = R^T nhat
        const float w0 = fmaf(R0, hx, fmaf(R3, hy, R6 * hz));
        const float w1 = fmaf(R1, hx, fmaf(R4, hy, R7 * hz));
        const float w2 = fmaf(R2, hx, fmaf(R5, hy, R8 * hz));
        // psi = pci + rn * w
        const float q0 = fmaf(rn, w0, c0);
        const float q1 = fmaf(rn, w1, c1);
        const float q2 = fmaf(rn, w2, c2);

        // argmax over 6 faces == max |w| axis, sign of w on that axis
        const float a0 = fabsf(w0), a1 = fabsf(w1), a2 = fabsf(w2);
        int ax = 0; float best = a0;
        if (a1 > best) { best = a1; ax = 1; }
        if (a2 > best) { best = a2; ax = 2; }
        const float wax = (ax == 0) ? w0 : ((ax == 1) ? w1 : w2);
        const float sgn = (wax > 0.f) ? 1.f : -1.f;

        // clamp, then override selected axis with +/- scale
        float p0 = fminf(fmaxf(q0, -s0), s0);
        float p1 = fminf(fmaxf(q1, -s1), s1);
        float p2 = fminf(fmaxf(q2, -s2), s2);
        if (ax == 0)      p0 = sgn * s0;
        else if (ax == 1) p1 = sgn * s1;
        else              p2 = sgn * s2;

        // log-domain superquadric surface point
        const float p0sq = fmaxf(p0 * p0, 1e-38f);
        const float p1sq = fmaxf(p1 * p1, 1e-38f);
        const float p2sq = fmaxf(p2 * p2, 1e-38f);
        const float r2   = p0sq + p1sq;
        const float rho2 = r2 + p2sq;          // >= min(scale)^2 >= 0.01

        const float Lr = flog2(r2);
        const float Lh = flog2(rho2);
        const float L0 = flog2(p0sq);
        const float L1 = flog2(p1sq);
        const float L2 = flog2(p2sq);

        const float tphi = he0 * (Lr - Lh);            // log2(gph)
        const float u    = fmaf(-he1, Lr, tphi);
        const float X = copysignf(s0 * fexp2(fmaf(he1, L0, u)), p0);
        const float Y = copysignf(s1 * fexp2(fmaf(he1, L1, u)), p1);
        const float Z = copysignf(s2 * fexp2(he0 * (L2 - Lh)), p2);

        const float dx = X - c0, dy = Y - c1, dz = Z - c2;
        rec = fmaf(dx * dx + dy * dy + dz * dz, akr[kk], rec);
    }

    // --- block reductions (deterministic) ---
    #pragma unroll
    for (int off = 16; off; off >>= 1)
        rec += __shfl_down_sync(0xffffffffu, rec, off);
    if (lane == 0) srec[warp] = rec;

    // assign column sums from sA: thread t sums 8 rows of column (t&15)
    {
        const int kcol = t & 15, chunk = t >> 4;   // 16 chunks x 8 rows = 128 rows
        float csum = 0.f;
        #pragma unroll
        for (int i = 0; i < 8; i++)
            csum += sA[(chunk * 8 + i) * 17 + kcol];
        scol2[t] = csum;
    }
    __syncthreads();

    if (t == 0) {
        float s = 0.f;
        #pragma unroll
        for (int w = 0; w < 8; w++) s += srec[w];
        float kp = skld[0] + skld[1] + skld[2] + skld[3];
        g_comb[blk] = s * (1.0f / (32.f * 4096.f)) + kp * (-0.5f * 0.001f / 32.f);
    }
    if (t < Kn) {
        float s = 0.f;
        #pragma unroll
        for (int c = 0; c < 16; c++) s += scol2[t + c * 16];
        g_col_partial[blk * Kn + t] = s;
    }

    // --- last-block-done: fused final reduction ---
    __threadfence();
    __syncthreads();
    if (t == 0) {
        unsigned int v = atomicAdd(&g_count, 1u);
        isLast = (v == GRIDA - 1);
    }
    __syncthreads();
    if (!isLast) return;
    __threadfence();

    float acc = g_comb[t] + g_comb[t + 256] + g_comb[t + 512] + g_comb[t + 768];

    // cs for (b,k) pairs p = t and p = t+256
    float cs0 = 0.f, cs1 = 0.f;
    {
        const int b0 = t >> 4, b1 = (t + 256) >> 4, kc = t & 15;
        #pragma unroll
        for (int nb2 = 0; nb2 < 32; nb2++) {
            cs0 += g_col_partial[((b0 * 32 + nb2) << 4) + kc];
            cs1 += g_col_partial[((b1 * 32 + nb2) << 4) + kc];
        }
        sfin[t]       = sqrtf(cs0 * (1.f / 4096.f) + 0.01f);
        sfin[t + 256] = sqrtf(cs1 * (1.f / 4096.f) + 0.01f);
    }

    // EXT: BCE-with-logits for pairs t, t+256 (weight 0.01)
    {
        const float l0 = exist[t], l1 = exist[t + 256];
        const float g0 = (cs0 > 24.f) ? 1.f : 0.f;
        const float g1 = (cs1 > 24.f) ? 1.f : 0.f;
        const float e0v = fmaxf(l0, 0.f) - l0 * g0 + log1pf(expf(-fabsf(l0)));
        const float e1v = fmaxf(l1, 0.f) - l1 * g1 + log1pf(expf(-fabsf(l1)));
        acc += (e0v + e1v) * (0.01f / 512.f);
    }

    // CST: 512 (b,k) pairs, 2 per thread (weight 0.1)
    {
        const int p0i = t * 3, p1i = (t + 256) * 3;
        float dx0 = pam[p0i]     - trans[p0i];
        float dy0 = pam[p0i + 1] - trans[p0i + 1];
        float dz0 = pam[p0i + 2] - trans[p0i + 2];
        float dx1 = pam[p1i]     - trans[p1i];
        float dy1 = pam[p1i + 1] - trans[p1i + 1];
        float dz1 = pam[p1i + 2] - trans[p1i + 2];
        acc += (sqrtf(dx0 * dx0 + dy0 * dy0 + dz0 * dz0) +
                sqrtf(dx1 * dx1 + dy1 * dy1 + dz1 * dz1)) * (0.1f / 512.f);
    }

    // SPS: per-b mean over k of sfin, squared (weight 0.1)
    __syncthreads();
    if (t < 32) {
        float m = 0.f;
        #pragma unroll
        for (int kk2 = 0; kk2 < 16; kk2++) m += sfin[t * 16 + kk2];
        m *= (1.f / 16.f);
        acc += m * m * (0.1f / 32.f);
    }

    // block reduction of acc
    #pragma unroll
    for (int off = 16; off; off >>= 1)
        acc += __shfl_down_sync(0xffffffffu, acc, off);
    __syncthreads();
    if (lane == 0) srec[warp] = acc;
    __syncthreads();
    if (t == 0) {
        float s = 0.f;
        #pragma unroll
        for (int w = 0; w < 8; w++) s += srec[w];
        out[0] = s;
        g_count = 0;   // reset for next graph replay
    }
}

extern "C" void kernel_launch(void* const* d_in, const int* in_sizes, int n_in,
                              void* d_out, int out_size)
{
    const float* pc      = (const float*)d_in[0];
    const float* normals = (const float*)d_in[1];
    const float* randn   = (const float*)d_in[2];
    const float* scale   = (const float*)d_in[3];
    const float* shapes  = (const float*)d_in[4];
    const float* rotate  = (const float*)d_in[5];
    const float* pam     = (const float*)d_in[6];
    const float* assign  = (const float*)d_in[7];
    const float* exist   = (const float*)d_in[8];
    const float* mu      = (const float*)d_in[9];
    const float* logvar  = (const float*)d_in[10];
    const float* trans   = (const float*)d_in[11];
    float* out = (float*)d_out;

    loss_fused_kernel<<<GRIDA, 256>>>(pc, normals, randn, scale, shapes, rotate,
                                      pam, assign, exist, mu, logvar, trans, out);
}